// round 2
// baseline (speedup 1.0000x reference)
#include <cuda_runtime.h>
#include <math.h>
#include <stdint.h>

#define NN      100000
#define EE      1600000
#define GG      512
#define INDIM   1024
#define HID     128
#define HEADS   4

// ---------------- static device scratch (no allocations allowed) ----------------
__device__ float g_X[NN * HID];        // node features between stages (51.2 MB)
__device__ float g_H[NN * HID];        // per-layer projected features  (51.2 MB)
__device__ float g_as[NN * HEADS];     // alpha_src per node/head
__device__ float g_ad[NN * HEADS];     // alpha_dst per node/head
__device__ int   g_rowptr[NN + 1];     // CSR row pointer by dst
__device__ int   g_cursor[NN];         // counts / scatter cursor
__device__ int   g_colsrc[EE];         // CSR src indices

// ---------------- small utility kernels ----------------
__global__ void zero_int_kernel(int* p, int n) {
    int i = blockIdx.x * blockDim.x + threadIdx.x;
    if (i < n) p[i] = 0;
}
__global__ void zero_float_kernel(float* p, int n) {
    int i = blockIdx.x * blockDim.x + threadIdx.x;
    if (i < n) p[i] = 0.0f;
}

// histogram of edge destinations into g_cursor (edge_index is int32: [2, E] row-major)
__global__ void hist_kernel(const int* __restrict__ ei) {
    int e = blockIdx.x * blockDim.x + threadIdx.x;
    if (e < EE) {
        int dst = ei[EE + e];
        atomicAdd(&g_cursor[dst], 1);
    }
}

// single-block exclusive scan of g_cursor[N] -> g_rowptr[N+1]
__global__ void scan_kernel() {
    __shared__ int sm[1024];
    int t = threadIdx.x;
    if (t == 0) g_rowptr[0] = 0;
    int carry = 0; // replicated identically across all threads
    for (int base = 0; base < NN; base += 1024) {
        int v = (base + t < NN) ? g_cursor[base + t] : 0;
        sm[t] = v;
        __syncthreads();
        #pragma unroll
        for (int off = 1; off < 1024; off <<= 1) {
            int add = (t >= off) ? sm[t - off] : 0;
            __syncthreads();
            sm[t] += add;
            __syncthreads();
        }
        if (base + t < NN) g_rowptr[base + t + 1] = carry + sm[t];
        int total = sm[1023];
        carry += total;
        __syncthreads();
    }
}

__global__ void copy_cursor_kernel() {
    int i = blockIdx.x * blockDim.x + threadIdx.x;
    if (i < NN) g_cursor[i] = g_rowptr[i];
}

__global__ void scatter_kernel(const int* __restrict__ ei) {
    int e = blockIdx.x * blockDim.x + threadIdx.x;
    if (e < EE) {
        int src = ei[e];
        int dst = ei[EE + e];
        int pos = atomicAdd(&g_cursor[dst], 1);
        g_colsrc[pos] = src;
    }
}

// ---------------- SGEMM: C[M,128] = act(A[M,K] @ B[K,128] + bias) ----------------
// BM=128, BN=128, BK=16, 256 threads, 8x8 micro-tile per thread.
__global__ __launch_bounds__(256)
void sgemm_kernel(const float* __restrict__ A, const float* __restrict__ B,
                  const float* __restrict__ bias, float* __restrict__ C,
                  int M, int K, int apply_gelu) {
    __shared__ float As[16][128];   // transposed A tile: As[k][m]
    __shared__ float Bs[16][128];   // Bs[k][n]

    const int t  = threadIdx.x;
    const int tx = t & 15;          // column group 0..15
    const int ty = t >> 4;          // row group    0..15
    const int row0 = blockIdx.y * 128;

    float acc[8][8];
    #pragma unroll
    for (int i = 0; i < 8; i++)
        #pragma unroll
        for (int j = 0; j < 8; j++) acc[i][j] = 0.0f;

    // A-load mapping: 2 float4 per thread: rows (t>>2) and (t>>2)+64, cols (t&3)*4
    const int a_r = t >> 2;
    const int a_c = (t & 3) << 2;
    // B-load mapping: 2 float4 per thread: rows (t>>5) and (t>>5)+8, cols (t&31)*4
    const int b_r = t >> 5;
    const int b_c = (t & 31) << 2;

    for (int k0 = 0; k0 < K; k0 += 16) {
        #pragma unroll
        for (int rr = 0; rr < 2; rr++) {
            int mrow = a_r + rr * 64;
            int grow = row0 + mrow;
            float4 v = make_float4(0.f, 0.f, 0.f, 0.f);
            if (grow < M) v = *(const float4*)&A[(size_t)grow * K + k0 + a_c];
            As[a_c + 0][mrow] = v.x;
            As[a_c + 1][mrow] = v.y;
            As[a_c + 2][mrow] = v.z;
            As[a_c + 3][mrow] = v.w;
        }
        #pragma unroll
        for (int rr = 0; rr < 2; rr++) {
            int krow = b_r + rr * 8;
            float4 v = *(const float4*)&B[(size_t)(k0 + krow) * HID + b_c];
            *(float4*)&Bs[krow][b_c] = v;
        }
        __syncthreads();

        #pragma unroll
        for (int kk = 0; kk < 16; kk++) {
            float4 a0 = *(const float4*)&As[kk][ty * 8];
            float4 a1 = *(const float4*)&As[kk][ty * 8 + 4];
            float4 b0 = *(const float4*)&Bs[kk][tx * 8];
            float4 b1 = *(const float4*)&Bs[kk][tx * 8 + 4];
            float av[8] = {a0.x, a0.y, a0.z, a0.w, a1.x, a1.y, a1.z, a1.w};
            float bv[8] = {b0.x, b0.y, b0.z, b0.w, b1.x, b1.y, b1.z, b1.w};
            #pragma unroll
            for (int i = 0; i < 8; i++)
                #pragma unroll
                for (int j = 0; j < 8; j++)
                    acc[i][j] = fmaf(av[i], bv[j], acc[i][j]);
        }
        __syncthreads();
    }

    // epilogue
    #pragma unroll
    for (int i = 0; i < 8; i++) {
        int grow = row0 + ty * 8 + i;
        if (grow >= M) continue;
        #pragma unroll
        for (int jj = 0; jj < 8; jj += 4) {
            float4 o;
            float vals[4];
            #pragma unroll
            for (int q = 0; q < 4; q++) {
                int col = tx * 8 + jj + q;
                float v = acc[i][jj + q];
                if (bias) v += bias[col];
                if (apply_gelu) {
                    // exact GELU: 0.5*x*(1+erf(x/sqrt(2)))
                    v = 0.5f * v * (1.0f + erff(v * 0.70710678118654752f));
                }
                vals[q] = v;
            }
            o.x = vals[0]; o.y = vals[1]; o.z = vals[2]; o.w = vals[3];
            *(float4*)&C[(size_t)grow * HID + tx * 8 + jj] = o;
        }
    }
}

// ---------------- per-node attention coefficients ----------------
// alpha_s[n,h] = dot(H[n, h*32:(h+1)*32], a_src[h]); same for alpha_d.
__global__ __launch_bounds__(256)
void alpha_kernel(const float* __restrict__ asrc, const float* __restrict__ adst) {
    int gtid = blockIdx.x * blockDim.x + threadIdx.x;
    int node = gtid >> 5;
    if (node >= NN) return;
    int lane = threadIdx.x & 31;
    float4 hv = ((const float4*)g_H)[node * 32 + lane];
    float4 av = ((const float4*)asrc)[lane];
    float4 dv = ((const float4*)adst)[lane];
    float s = hv.x * av.x + hv.y * av.y + hv.z * av.z + hv.w * av.w;
    float d = hv.x * dv.x + hv.y * dv.y + hv.z * dv.z + hv.w * dv.w;
    #pragma unroll
    for (int off = 4; off >= 1; off >>= 1) {
        s += __shfl_xor_sync(0xffffffffu, s, off);
        d += __shfl_xor_sync(0xffffffffu, d, off);
    }
    if ((lane & 7) == 0) {
        int head = lane >> 3;
        g_as[node * HEADS + head] = s;
        g_ad[node * HEADS + head] = d;
    }
}

// ---------------- warp-per-node GAT aggregation with online softmax ----------------
// Lane l owns float4 = channels [4*(l%8) .. 4*(l%8)+3] of head l/8.
// Self-loop processed explicitly (not stored in CSR).
__global__ __launch_bounds__(256)
void gat_agg_kernel(const float* __restrict__ bias, float* __restrict__ Xout) {
    int gtid = blockIdx.x * blockDim.x + threadIdx.x;
    int node = gtid >> 5;
    if (node >= NN) return;
    int lane = threadIdx.x & 31;
    int head = lane >> 3;

    const float4* H4 = (const float4*)g_H;
    float ad = g_ad[node * HEADS + head];

    // self loop (always present)
    float e0 = g_as[node * HEADS + head] + ad;
    e0 = e0 > 0.f ? e0 : 0.2f * e0;
    float m = e0;
    float dsum = 1.0f;
    float4 acc = H4[node * 32 + lane];

    int beg = g_rowptr[node];
    int end = g_rowptr[node + 1];
    for (int i = beg; i < end; i++) {
        int src = g_colsrc[i];
        float e = g_as[src * HEADS + head] + ad;
        e = e > 0.f ? e : 0.2f * e;
        float4 hv = H4[src * 32 + lane];
        float mn = fmaxf(m, e);
        float sc = __expf(m - mn);
        float w  = __expf(e - mn);
        dsum = fmaf(dsum, sc, w);
        acc.x = fmaf(acc.x, sc, w * hv.x);
        acc.y = fmaf(acc.y, sc, w * hv.y);
        acc.z = fmaf(acc.z, sc, w * hv.z);
        acc.w = fmaf(acc.w, sc, w * hv.w);
        m = mn;
    }

    float inv = 1.0f / dsum;
    float4 bv = ((const float4*)bias)[lane];
    float4 o;
    o.x = fmaxf(fmaf(acc.x, inv, bv.x), 0.0f);
    o.y = fmaxf(fmaf(acc.y, inv, bv.y), 0.0f);
    o.z = fmaxf(fmaf(acc.z, inv, bv.z), 0.0f);
    o.w = fmaxf(fmaf(acc.w, inv, bv.w), 0.0f);
    ((float4*)Xout)[node * 32 + lane] = o;
}

// ---------------- global add pool ----------------
__global__ void pool_kernel(const int* __restrict__ batch, float* __restrict__ out) {
    int idx = blockIdx.x * blockDim.x + threadIdx.x;
    if (idx >= NN * HID) return;
    int nd = idx >> 7;
    int c  = idx & 127;
    int g  = batch[nd];
    atomicAdd(&out[g * HID + c], g_X[idx]);
}

// ---------------- launch ----------------
extern "C" void kernel_launch(void* const* d_in, const int* in_sizes, int n_in,
                              void* d_out, int out_size) {
    const float* nf    = (const float*)d_in[0];
    const int*   ei    = (const int*)d_in[1];    // int32 (JAX x64 disabled)
    const int*   batch = (const int*)d_in[2];    // int32
    const float* W1    = (const float*)d_in[3];
    const float* b1    = (const float*)d_in[4];
    const float* Wg    = (const float*)d_in[5];
    const float* a_src = (const float*)d_in[6];
    const float* a_dst = (const float*)d_in[7];
    const float* bg    = (const float*)d_in[8];
    float* out = (float*)d_out;

    float *pX, *pH;
    cudaGetSymbolAddress((void**)&pX, g_X);
    cudaGetSymbolAddress((void**)&pH, g_H);
    int* pCursor;
    cudaGetSymbolAddress((void**)&pCursor, g_cursor);

    // ---- CSR build by destination ----
    zero_int_kernel<<<(NN + 255) / 256, 256>>>(pCursor, NN);
    hist_kernel<<<(EE + 255) / 256, 256>>>(ei);
    scan_kernel<<<1, 1024>>>();
    copy_cursor_kernel<<<(NN + 255) / 256, 256>>>();
    scatter_kernel<<<(EE + 255) / 256, 256>>>(ei);

    // ---- input featurizer: X = gelu(nf @ W1 + b1) ----
    {
        dim3 grid(1, (NN + 127) / 128);
        sgemm_kernel<<<grid, 256>>>(nf, W1, b1, pX, NN, INDIM, 1);
    }

    // ---- GAT layers ----
    for (int l = 0; l < 2; l++) {
        dim3 grid(1, (NN + 127) / 128);
        sgemm_kernel<<<grid, 256>>>(pX, Wg + (size_t)l * HID * HID, nullptr, pH, NN, HID, 0);
        alpha_kernel<<<(NN * 32 + 255) / 256, 256>>>(a_src + l * HEADS * 32, a_dst + l * HEADS * 32);
        gat_agg_kernel<<<(NN * 32 + 255) / 256, 256>>>(bg + l * HID, pX);
    }

    // ---- global add pool ----
    zero_float_kernel<<<(GG * HID + 255) / 256, 256>>>(out, GG * HID);
    pool_kernel<<<(NN * HID + 255) / 256, 256>>>(batch, out);
}

// round 4
// speedup vs baseline: 1.6692x; 1.6692x over previous
#include <cuda_runtime.h>
#include <cuda_bf16.h>
#include <math.h>
#include <stdint.h>

#define NN      100000
#define EE      1600000
#define GG      512
#define INDIM   1024
#define HID     128
#define HEADS   4

// ================= static device scratch =================
__device__ float g_X[NN * HID];
__device__ float g_H[NN * HID];
__device__ float g_as[NN * HEADS];
__device__ float g_ad[NN * HEADS];
__device__ int   g_rowptr[NN + 1];
__device__ int   g_cursor[NN];
__device__ int   g_colsrc[EE];
__device__ __nv_bfloat16 g_W1T_hi[HID * INDIM];   // [n][k] row-major
__device__ __nv_bfloat16 g_W1T_lo[HID * INDIM];
__device__ __nv_bfloat16 g_WgT_hi[2 * HID * HID];
__device__ __nv_bfloat16 g_WgT_lo[2 * HID * HID];

// ================= small utility kernels =================
__global__ void zero_int_kernel(int* p, int n) {
    int i = blockIdx.x * blockDim.x + threadIdx.x;
    if (i < n) p[i] = 0;
}
__global__ void zero_float_kernel(float* p, int n) {
    int i = blockIdx.x * blockDim.x + threadIdx.x;
    if (i < n) p[i] = 0.0f;
}
__global__ void hist_kernel(const int* __restrict__ ei) {
    int e = blockIdx.x * blockDim.x + threadIdx.x;
    if (e < EE) atomicAdd(&g_cursor[ei[EE + e]], 1);
}
__global__ void scan_kernel() {
    __shared__ int sm[1024];
    int t = threadIdx.x;
    if (t == 0) g_rowptr[0] = 0;
    int carry = 0;
    for (int base = 0; base < NN; base += 1024) {
        int v = (base + t < NN) ? g_cursor[base + t] : 0;
        sm[t] = v;
        __syncthreads();
        #pragma unroll
        for (int off = 1; off < 1024; off <<= 1) {
            int add = (t >= off) ? sm[t - off] : 0;
            __syncthreads();
            sm[t] += add;
            __syncthreads();
        }
        if (base + t < NN) g_rowptr[base + t + 1] = carry + sm[t];
        carry += sm[1023];
        __syncthreads();
    }
}
__global__ void copy_cursor_kernel() {
    int i = blockIdx.x * blockDim.x + threadIdx.x;
    if (i < NN) g_cursor[i] = g_rowptr[i];
}
__global__ void scatter_kernel(const int* __restrict__ ei) {
    int e = blockIdx.x * blockDim.x + threadIdx.x;
    if (e < EE) {
        int src = ei[e];
        int dst = ei[EE + e];
        g_colsrc[atomicAdd(&g_cursor[dst], 1)] = src;
    }
}

// ================= weight prep: transpose + split-bf16 =================
__global__ void prep_w1_kernel(const float* __restrict__ W) {
    int idx = blockIdx.x * blockDim.x + threadIdx.x;   // n*1024 + k
    if (idx >= HID * INDIM) return;
    int n = idx >> 10, k = idx & 1023;
    float w = W[k * HID + n];
    __nv_bfloat16 h = __float2bfloat16(w);
    g_W1T_hi[idx] = h;
    g_W1T_lo[idx] = __float2bfloat16(w - __bfloat162float(h));
}
__global__ void prep_wg_kernel(const float* __restrict__ W) {
    int idx = blockIdx.x * blockDim.x + threadIdx.x;   // l*16384 + n*128 + k
    if (idx >= 2 * HID * HID) return;
    int l = idx >> 14, n = (idx >> 7) & 127, k = idx & 127;
    float w = W[l * HID * HID + k * HID + n];
    __nv_bfloat16 h = __float2bfloat16(w);
    g_WgT_hi[idx] = h;
    g_WgT_lo[idx] = __float2bfloat16(w - __bfloat162float(h));
}

// ================= mma.sync helpers =================
__device__ __forceinline__ uint32_t smem_u32(const void* p) {
    uint32_t a;
    asm("{ .reg .u64 t; cvta.to.shared.u64 t, %1; cvt.u32.u64 %0, t; }" : "=r"(a) : "l"(p));
    return a;
}
__device__ __forceinline__ void ldmatrix_x4(uint32_t& r0, uint32_t& r1, uint32_t& r2, uint32_t& r3,
                                            uint32_t addr) {
    asm volatile("ldmatrix.sync.aligned.m8n8.x4.shared.b16 {%0,%1,%2,%3}, [%4];"
                 : "=r"(r0), "=r"(r1), "=r"(r2), "=r"(r3) : "r"(addr));
}
__device__ __forceinline__ void mma_bf16(float* c, const uint32_t* a, const uint32_t* b) {
    asm volatile(
        "mma.sync.aligned.m16n8k16.row.col.f32.bf16.bf16.f32 "
        "{%0,%1,%2,%3}, {%4,%5,%6,%7}, {%8,%9}, {%0,%1,%2,%3};"
        : "+f"(c[0]), "+f"(c[1]), "+f"(c[2]), "+f"(c[3])
        : "r"(a[0]), "r"(a[1]), "r"(a[2]), "r"(a[3]), "r"(b[0]), "r"(b[1]));
}
__device__ __forceinline__ uint32_t pack2(__nv_bfloat16 a, __nv_bfloat16 b) {
    __nv_bfloat162 p; p.x = a; p.y = b;
    return *(uint32_t*)&p;
}

// ================= HMMA split-bf16 GEMM =================
// C[M,128] = act(A[M,K] @ W[K,128] (+bias)); W pre-transposed/split: BT[128][K] bf16 hi/lo.
// CTA tile 128x128, 8 warps (4x2), warp tile 32x64, BK=32, SMEM ld = 40 bf16 (80 B).
#define LDP 40

__global__ __launch_bounds__(256)
void mma_gemm_kernel(const float* __restrict__ A,
                     const __nv_bfloat16* __restrict__ BThi,
                     const __nv_bfloat16* __restrict__ BTlo,
                     const float* __restrict__ bias,
                     float* __restrict__ C,
                     int M, int K, int apply_gelu) {
    __shared__ __nv_bfloat16 sAh[128 * LDP];
    __shared__ __nv_bfloat16 sAl[128 * LDP];
    __shared__ __nv_bfloat16 sBh[128 * LDP];
    __shared__ __nv_bfloat16 sBl[128 * LDP];

    const int t = threadIdx.x;
    const int lane = t & 31, wid = t >> 5;
    const int wm = wid & 3;          // 0..3 -> rows wm*32
    const int wn = wid >> 2;         // 0..1 -> cols wn*64
    const int row0 = blockIdx.x * 128;

    float acc[2][8][4];
    #pragma unroll
    for (int i = 0; i < 2; i++)
        #pragma unroll
        for (int j = 0; j < 8; j++)
            #pragma unroll
            for (int q = 0; q < 4; q++) acc[i][j][q] = 0.0f;

    const uint32_t uAh = smem_u32(sAh), uAl = smem_u32(sAl);
    const uint32_t uBh = smem_u32(sBh), uBl = smem_u32(sBl);

    // ldmatrix address precompute (byte offsets within tile; row stride = 80 B)
    // A: tile base row = wm*32 + mf*16; thread row = lane%16; col8 = (lane>=16)
    const int a_lrow = lane & 15;
    const int a_c8   = (lane >> 4) << 3;          // 0 or 8 (elements)
    // B: pair tile base row = wn*64 + pair*16; thread row = lane%8 + ((lane>>4)&1 ? 8:0)
    // groups: g0 n0-7@k0, g1 n0-7@k8, g2 n8-15@k0, g3 n8-15@k8
    const int b_lrow = (lane & 7) + ((lane >> 4) << 3);
    const int b_c8   = ((lane >> 3) & 1) << 3;    // 0 or 8

    const int nchunks = K >> 5;
    for (int c = 0; c < nchunks; c++) {
        const int k0 = c << 5;

        // ---- load A [128 x 32] fp32 -> split bf16 ----
        #pragma unroll
        for (int j = 0; j < 4; j++) {
            int idx = t + j * 256;                // 0..1023
            int r = idx >> 3, colv = (idx & 7) << 2;
            float4 v = make_float4(0.f, 0.f, 0.f, 0.f);
            int gr = row0 + r;
            if (gr < M) v = *(const float4*)&A[(size_t)gr * K + k0 + colv];
            __nv_bfloat16 h0 = __float2bfloat16(v.x), h1 = __float2bfloat16(v.y);
            __nv_bfloat16 h2 = __float2bfloat16(v.z), h3 = __float2bfloat16(v.w);
            uint2 hv, lv;
            hv.x = pack2(h0, h1); hv.y = pack2(h2, h3);
            lv.x = pack2(__float2bfloat16(v.x - __bfloat162float(h0)),
                         __float2bfloat16(v.y - __bfloat162float(h1)));
            lv.y = pack2(__float2bfloat16(v.z - __bfloat162float(h2)),
                         __float2bfloat16(v.w - __bfloat162float(h3)));
            *(uint2*)&sAh[r * LDP + colv] = hv;
            *(uint2*)&sAl[r * LDP + colv] = lv;
        }
        // ---- load B [128 x 32] bf16 hi/lo ----
        #pragma unroll
        for (int j = 0; j < 2; j++) {
            int idx = t + j * 256;                // 0..511
            int r = idx >> 2, colv = (idx & 3) << 3;
            size_t go = (size_t)r * K + k0 + colv;
            *(uint4*)&sBh[r * LDP + colv] = *(const uint4*)&BThi[go];
            *(uint4*)&sBl[r * LDP + colv] = *(const uint4*)&BTlo[go];
        }
        __syncthreads();

        #pragma unroll
        for (int ks = 0; ks < 2; ks++) {
            const int kc = ks * 16;
            uint32_t ah[2][4], al[2][4];
            #pragma unroll
            for (int mf = 0; mf < 2; mf++) {
                uint32_t off = (uint32_t)((wm * 32 + mf * 16 + a_lrow) * 80 + (kc + a_c8) * 2);
                ldmatrix_x4(ah[mf][0], ah[mf][1], ah[mf][2], ah[mf][3], uAh + off);
                ldmatrix_x4(al[mf][0], al[mf][1], al[mf][2], al[mf][3], uAl + off);
            }
            uint32_t bh[8][2], bl[8][2];
            #pragma unroll
            for (int p = 0; p < 4; p++) {
                uint32_t off = (uint32_t)((wn * 64 + p * 16 + b_lrow) * 80 + (kc + b_c8) * 2);
                uint32_t r0, r1, r2, r3;
                ldmatrix_x4(r0, r1, r2, r3, uBh + off);
                bh[2*p][0] = r0; bh[2*p][1] = r1; bh[2*p+1][0] = r2; bh[2*p+1][1] = r3;
                ldmatrix_x4(r0, r1, r2, r3, uBl + off);
                bl[2*p][0] = r0; bl[2*p][1] = r1; bl[2*p+1][0] = r2; bl[2*p+1][1] = r3;
            }
            #pragma unroll
            for (int mf = 0; mf < 2; mf++)
                #pragma unroll
                for (int nf = 0; nf < 8; nf++) {
                    mma_bf16(acc[mf][nf], ah[mf], bh[nf]);
                    mma_bf16(acc[mf][nf], ah[mf], bl[nf]);
                    mma_bf16(acc[mf][nf], al[mf], bh[nf]);
                }
        }
        __syncthreads();
    }

    // ---- epilogue ----
    const int crow = lane >> 2;
    const int ccol = (lane & 3) << 1;
    #pragma unroll
    for (int mf = 0; mf < 2; mf++) {
        int rbase = row0 + wm * 32 + mf * 16 + crow;
        #pragma unroll
        for (int nf = 0; nf < 8; nf++) {
            int col = wn * 64 + nf * 8 + ccol;
            #pragma unroll
            for (int half = 0; half < 2; half++) {
                int r = rbase + half * 8;
                if (r >= M) continue;
                float v0 = acc[mf][nf][half * 2 + 0];
                float v1 = acc[mf][nf][half * 2 + 1];
                if (bias) { v0 += bias[col]; v1 += bias[col + 1]; }
                if (apply_gelu) {
                    v0 = 0.5f * v0 * (1.0f + erff(v0 * 0.70710678118654752f));
                    v1 = 0.5f * v1 * (1.0f + erff(v1 * 0.70710678118654752f));
                }
                float2 o; o.x = v0; o.y = v1;
                *(float2*)&C[(size_t)r * HID + col] = o;
            }
        }
    }
}

// ================= attention coefficients =================
__global__ __launch_bounds__(256)
void alpha_kernel(const float* __restrict__ asrc, const float* __restrict__ adst) {
    int gtid = blockIdx.x * blockDim.x + threadIdx.x;
    int node = gtid >> 5;
    if (node >= NN) return;
    int lane = threadIdx.x & 31;
    float4 hv = ((const float4*)g_H)[node * 32 + lane];
    float4 av = ((const float4*)asrc)[lane];
    float4 dv = ((const float4*)adst)[lane];
    float s = hv.x * av.x + hv.y * av.y + hv.z * av.z + hv.w * av.w;
    float d = hv.x * dv.x + hv.y * dv.y + hv.z * dv.z + hv.w * dv.w;
    #pragma unroll
    for (int off = 4; off >= 1; off >>= 1) {
        s += __shfl_xor_sync(0xffffffffu, s, off);
        d += __shfl_xor_sync(0xffffffffu, d, off);
    }
    if ((lane & 7) == 0) {
        int head = lane >> 3;
        g_as[node * HEADS + head] = s;
        g_ad[node * HEADS + head] = d;
    }
}

// ================= warp-per-node GAT aggregation (online softmax) =================
__global__ __launch_bounds__(256)
void gat_agg_kernel(const float* __restrict__ bias, float* __restrict__ Xout) {
    int gtid = blockIdx.x * blockDim.x + threadIdx.x;
    int node = gtid >> 5;
    if (node >= NN) return;
    int lane = threadIdx.x & 31;
    int head = lane >> 3;

    const float4* H4 = (const float4*)g_H;
    float ad = g_ad[node * HEADS + head];

    float e0 = g_as[node * HEADS + head] + ad;     // self loop
    e0 = e0 > 0.f ? e0 : 0.2f * e0;
    float m = e0;
    float dsum = 1.0f;
    float4 acc = H4[node * 32 + lane];

    int beg = g_rowptr[node];
    int end = g_rowptr[node + 1];
    for (int i = beg; i < end; i++) {
        int src = g_colsrc[i];
        float e = g_as[src * HEADS + head] + ad;
        e = e > 0.f ? e : 0.2f * e;
        float4 hv = H4[src * 32 + lane];
        float mn = fmaxf(m, e);
        float sc = __expf(m - mn);
        float w  = __expf(e - mn);
        dsum = fmaf(dsum, sc, w);
        acc.x = fmaf(acc.x, sc, w * hv.x);
        acc.y = fmaf(acc.y, sc, w * hv.y);
        acc.z = fmaf(acc.z, sc, w * hv.z);
        acc.w = fmaf(acc.w, sc, w * hv.w);
        m = mn;
    }
    float inv = 1.0f / dsum;
    float4 bv = ((const float4*)bias)[lane];
    float4 o;
    o.x = fmaxf(fmaf(acc.x, inv, bv.x), 0.0f);
    o.y = fmaxf(fmaf(acc.y, inv, bv.y), 0.0f);
    o.z = fmaxf(fmaf(acc.z, inv, bv.z), 0.0f);
    o.w = fmaxf(fmaf(acc.w, inv, bv.w), 0.0f);
    ((float4*)Xout)[node * 32 + lane] = o;
}

// ================= global add pool =================
__global__ void pool_kernel(const int* __restrict__ batch, float* __restrict__ out) {
    int idx = blockIdx.x * blockDim.x + threadIdx.x;
    if (idx >= NN * HID) return;
    int nd = idx >> 7;
    int c  = idx & 127;
    atomicAdd(&out[batch[nd] * HID + c], g_X[idx]);
}

// ================= launch =================
extern "C" void kernel_launch(void* const* d_in, const int* in_sizes, int n_in,
                              void* d_out, int out_size) {
    const float* nf    = (const float*)d_in[0];
    const int*   ei    = (const int*)d_in[1];
    const int*   batch = (const int*)d_in[2];
    const float* W1    = (const float*)d_in[3];
    const float* b1    = (const float*)d_in[4];
    const float* Wg    = (const float*)d_in[5];
    const float* a_src = (const float*)d_in[6];
    const float* a_dst = (const float*)d_in[7];
    const float* bg    = (const float*)d_in[8];
    float* out = (float*)d_out;

    float *pX, *pH;
    cudaGetSymbolAddress((void**)&pX, g_X);
    cudaGetSymbolAddress((void**)&pH, g_H);
    int* pCursor;
    cudaGetSymbolAddress((void**)&pCursor, g_cursor);
    __nv_bfloat16 *pW1hi, *pW1lo, *pWghi, *pWglo;
    cudaGetSymbolAddress((void**)&pW1hi, g_W1T_hi);
    cudaGetSymbolAddress((void**)&pW1lo, g_W1T_lo);
    cudaGetSymbolAddress((void**)&pWghi, g_WgT_hi);
    cudaGetSymbolAddress((void**)&pWglo, g_WgT_lo);

    // ---- weight prep (transpose + split bf16) ----
    prep_w1_kernel<<<(HID * INDIM + 255) / 256, 256>>>(W1);
    prep_wg_kernel<<<(2 * HID * HID + 255) / 256, 256>>>(Wg);

    // ---- CSR build by destination ----
    zero_int_kernel<<<(NN + 255) / 256, 256>>>(pCursor, NN);
    hist_kernel<<<(EE + 255) / 256, 256>>>(ei);
    scan_kernel<<<1, 1024>>>();
    copy_cursor_kernel<<<(NN + 255) / 256, 256>>>();
    scatter_kernel<<<(EE + 255) / 256, 256>>>(ei);

    const int gemm_grid = (NN + 127) / 128;

    // ---- X = gelu(nf @ W1 + b1)  (HMMA split-bf16) ----
    mma_gemm_kernel<<<gemm_grid, 256>>>(nf, pW1hi, pW1lo, b1, pX, NN, INDIM, 1);

    // ---- GAT layers ----
    for (int l = 0; l < 2; l++) {
        mma_gemm_kernel<<<gemm_grid, 256>>>(
            pX, pWghi + (size_t)l * HID * HID, pWglo + (size_t)l * HID * HID,
            nullptr, pH, NN, HID, 0);
        alpha_kernel<<<(NN * 32 + 255) / 256, 256>>>(a_src + l * HEADS * 32, a_dst + l * HEADS * 32);
        gat_agg_kernel<<<(NN * 32 + 255) / 256, 256>>>(bg + l * HID, pX);
    }

    // ---- global add pool ----
    zero_float_kernel<<<(GG * HID + 255) / 256, 256>>>(out, GG * HID);
    pool_kernel<<<(NN * HID + 255) / 256, 256>>>(batch, out);
}

// round 5
// speedup vs baseline: 1.8850x; 1.1293x over previous
#include <cuda_runtime.h>
#include <cuda_bf16.h>
#include <math.h>
#include <stdint.h>

#define NN      100000
#define EE      1600000
#define GG      512
#define INDIM   1024
#define HID     128
#define HEADS   4
#define LDP     40          // smem row pitch in bf16 elems (80 B: 16B-aligned, ldmatrix conflict-free)

// ================= static device scratch =================
__device__ float g_X[NN * HID];
__device__ float g_H[NN * HID];
__device__ float g_as[NN * HEADS];
__device__ float g_ad[NN * HEADS];
__device__ int   g_rowptr[NN + 1];
__device__ int   g_cursor[NN];
__device__ int   g_colsrc[EE];
__device__ int   g_blocksum[128];
__device__ int   g_blockoff[128];
__device__ int   g_gstart[GG + 1];
__device__ __nv_bfloat16 g_W1T_hi[HID * INDIM];   // [n][k]
__device__ __nv_bfloat16 g_W1T_lo[HID * INDIM];
__device__ __nv_bfloat16 g_WgT_hi[2 * HID * HID];
__device__ __nv_bfloat16 g_WgT_lo[2 * HID * HID];

// ================= utility kernels =================
__global__ void zero_int_kernel(int* p, int n) {
    int i = blockIdx.x * blockDim.x + threadIdx.x;
    if (i < n) p[i] = 0;
}
__global__ void hist_kernel(const int* __restrict__ ei) {
    int e = blockIdx.x * blockDim.x + threadIdx.x;
    if (e < EE) atomicAdd(&g_cursor[ei[EE + e]], 1);
}

// ---- 3-phase scan: per-block inclusive scan + block sums ----
__global__ void scan_block_kernel() {        // grid 98, block 1024
    __shared__ int sm[1024];
    int b = blockIdx.x, t = threadIdx.x;
    int i = b * 1024 + t;
    int v = (i < NN) ? g_cursor[i] : 0;
    sm[t] = v;
    __syncthreads();
    #pragma unroll
    for (int off = 1; off < 1024; off <<= 1) {
        int add = (t >= off) ? sm[t - off] : 0;
        __syncthreads();
        sm[t] += add;
        __syncthreads();
    }
    if (i < NN) g_rowptr[i + 1] = sm[t];
    if (t == 1023) g_blocksum[b] = sm[1023];
}
__global__ void scan_sums_kernel(int nblocks) {  // 1 block, 128 threads
    __shared__ int sm[128];
    int t = threadIdx.x;
    sm[t] = (t < nblocks) ? g_blocksum[t] : 0;
    __syncthreads();
    #pragma unroll
    for (int off = 1; off < 128; off <<= 1) {
        int add = (t >= off) ? sm[t - off] : 0;
        __syncthreads();
        sm[t] += add;
        __syncthreads();
    }
    g_blockoff[t] = (t == 0) ? 0 : sm[t - 1];
}
__global__ void scan_add_kernel() {           // grid 98, block 1024
    int b = blockIdx.x, t = threadIdx.x;
    int i = b * 1024 + t;
    if (i < NN) g_rowptr[i + 1] += g_blockoff[b];
    if (i == 0) g_rowptr[0] = 0;
}
__global__ void copy_cursor_kernel() {
    int i = blockIdx.x * blockDim.x + threadIdx.x;
    if (i < NN) g_cursor[i] = g_rowptr[i];
}
__global__ void scatter_kernel(const int* __restrict__ ei) {
    int e = blockIdx.x * blockDim.x + threadIdx.x;
    if (e < EE) {
        int src = ei[e];
        int dst = ei[EE + e];
        g_colsrc[atomicAdd(&g_cursor[dst], 1)] = src;
    }
}

// ---- graph boundaries from sorted batch ----
__global__ void gstart_kernel(const int* __restrict__ batch) {
    int i = blockIdx.x * blockDim.x + threadIdx.x;
    if (i >= NN) return;
    int b = batch[i];
    int prev = (i == 0) ? -1 : batch[i - 1];
    for (int g = prev + 1; g <= b; g++) g_gstart[g] = i;
    if (i == NN - 1)
        for (int g = b + 1; g <= GG; g++) g_gstart[g] = NN;
}

// ================= weight prep: transpose + split-bf16 =================
__global__ void prep_w1_kernel(const float* __restrict__ W) {
    int idx = blockIdx.x * blockDim.x + threadIdx.x;
    if (idx >= HID * INDIM) return;
    int n = idx >> 10, k = idx & 1023;
    float w = W[k * HID + n];
    __nv_bfloat16 h = __float2bfloat16(w);
    g_W1T_hi[idx] = h;
    g_W1T_lo[idx] = __float2bfloat16(w - __bfloat162float(h));
}
__global__ void prep_wg_kernel(const float* __restrict__ W) {
    int idx = blockIdx.x * blockDim.x + threadIdx.x;
    if (idx >= 2 * HID * HID) return;
    int l = idx >> 14, n = (idx >> 7) & 127, k = idx & 127;
    float w = W[l * HID * HID + k * HID + n];
    __nv_bfloat16 h = __float2bfloat16(w);
    g_WgT_hi[idx] = h;
    g_WgT_lo[idx] = __float2bfloat16(w - __bfloat162float(h));
}

// ================= mma helpers =================
__device__ __forceinline__ uint32_t smem_u32(const void* p) {
    uint32_t a;
    asm("{ .reg .u64 t; cvta.to.shared.u64 t, %1; cvt.u32.u64 %0, t; }" : "=r"(a) : "l"(p));
    return a;
}
__device__ __forceinline__ void ldmatrix_x4(uint32_t& r0, uint32_t& r1, uint32_t& r2, uint32_t& r3,
                                            uint32_t addr) {
    asm volatile("ldmatrix.sync.aligned.m8n8.x4.shared.b16 {%0,%1,%2,%3}, [%4];"
                 : "=r"(r0), "=r"(r1), "=r"(r2), "=r"(r3) : "r"(addr));
}
__device__ __forceinline__ void mma_bf16(float* c, const uint32_t* a, const uint32_t* b) {
    asm volatile(
        "mma.sync.aligned.m16n8k16.row.col.f32.bf16.bf16.f32 "
        "{%0,%1,%2,%3}, {%4,%5,%6,%7}, {%8,%9}, {%0,%1,%2,%3};"
        : "+f"(c[0]), "+f"(c[1]), "+f"(c[2]), "+f"(c[3])
        : "r"(a[0]), "r"(a[1]), "r"(a[2]), "r"(a[3]), "r"(b[0]), "r"(b[1]));
}
__device__ __forceinline__ uint32_t pack2(__nv_bfloat16 a, __nv_bfloat16 b) {
    __nv_bfloat162 p; p.x = a; p.y = b;
    return *(uint32_t*)&p;
}
__device__ __forceinline__ void cp_async16(uint32_t dst, const void* src) {
    asm volatile("cp.async.cg.shared.global [%0], [%1], 16;" :: "r"(dst), "l"(src));
}
#define CP_COMMIT() asm volatile("cp.async.commit_group;" ::: "memory")
#define CP_WAIT0()  asm volatile("cp.async.wait_group 0;" ::: "memory")

// ================= pipelined HMMA split-bf16 GEMM =================
// C[M,128] = act(A[M,K] @ W[K,128] (+bias)); W pre-split/transposed BT[128][K] hi/lo.
// CTA 128x128, 8 warps (4x2), warp 32x64, BK=32, 2-stage smem pipeline.
// Stage layout (bytes): Ah @0, Al @10240, Bh @20480, Bl @30720; stage stride 40960.
#define STAGE_BYTES 40960
#define TCG_SMEM    (2 * STAGE_BYTES)

__global__ __launch_bounds__(256)
void mma_gemm_kernel(const float* __restrict__ A,
                     const __nv_bfloat16* __restrict__ BThi,
                     const __nv_bfloat16* __restrict__ BTlo,
                     const float* __restrict__ bias,
                     float* __restrict__ C,
                     int M, int K, int apply_gelu) {
    extern __shared__ char dsm[];

    const int t = threadIdx.x;
    const int lane = t & 31, wid = t >> 5;
    const int wm = wid & 3;
    const int wn = wid >> 2;
    const int row0 = blockIdx.x * 128;

    float acc[2][8][4];
    #pragma unroll
    for (int i = 0; i < 2; i++)
        #pragma unroll
        for (int j = 0; j < 8; j++)
            #pragma unroll
            for (int q = 0; q < 4; q++) acc[i][j][q] = 0.0f;

    const int a_lrow = lane & 15;
    const int a_c8   = (lane >> 4) << 3;
    const int b_lrow = (lane & 7) + ((lane >> 4) << 3);
    const int b_c8   = ((lane >> 3) & 1) << 3;

    const int nchunks = K >> 5;
    float4 areg[4];

    // ---- prologue: chunk 0 ----
    {
        const int k0 = 0;
        #pragma unroll
        for (int j = 0; j < 4; j++) {
            int idx = t + j * 256;
            int r = idx >> 3, colv = (idx & 7) << 2;
            int gr = row0 + r;
            areg[j] = (gr < M) ? *(const float4*)&A[(size_t)gr * K + k0 + colv]
                               : make_float4(0.f, 0.f, 0.f, 0.f);
        }
        char* st = dsm;
        #pragma unroll
        for (int j = 0; j < 2; j++) {
            int idx = t + j * 256;
            int r = idx >> 2, colv = (idx & 3) << 3;
            uint32_t off = (uint32_t)((r * LDP + colv) * 2);
            cp_async16(smem_u32(st + 20480 + off), BThi + (size_t)r * K + k0 + colv);
            cp_async16(smem_u32(st + 30720 + off), BTlo + (size_t)r * K + k0 + colv);
        }
        CP_COMMIT();
        __nv_bfloat16* sAh = (__nv_bfloat16*)(st);
        __nv_bfloat16* sAl = (__nv_bfloat16*)(st + 10240);
        #pragma unroll
        for (int j = 0; j < 4; j++) {
            int idx = t + j * 256;
            int r = idx >> 3, colv = (idx & 7) << 2;
            float4 v = areg[j];
            __nv_bfloat16 h0 = __float2bfloat16(v.x), h1 = __float2bfloat16(v.y);
            __nv_bfloat16 h2 = __float2bfloat16(v.z), h3 = __float2bfloat16(v.w);
            uint2 hv, lv;
            hv.x = pack2(h0, h1); hv.y = pack2(h2, h3);
            lv.x = pack2(__float2bfloat16(v.x - __bfloat162float(h0)),
                         __float2bfloat16(v.y - __bfloat162float(h1)));
            lv.y = pack2(__float2bfloat16(v.z - __bfloat162float(h2)),
                         __float2bfloat16(v.w - __bfloat162float(h3)));
            *(uint2*)&sAh[r * LDP + colv] = hv;
            *(uint2*)&sAl[r * LDP + colv] = lv;
        }
        CP_WAIT0();
        __syncthreads();
    }

    for (int c = 0; c < nchunks; c++) {
        char* cur = dsm + (c & 1) * STAGE_BYTES;
        char* nxt = dsm + ((c + 1) & 1) * STAGE_BYTES;
        const bool more = (c + 1) < nchunks;

        // issue next-chunk loads before compute
        if (more) {
            const int k0 = (c + 1) << 5;
            #pragma unroll
            for (int j = 0; j < 4; j++) {
                int idx = t + j * 256;
                int r = idx >> 3, colv = (idx & 7) << 2;
                int gr = row0 + r;
                areg[j] = (gr < M) ? *(const float4*)&A[(size_t)gr * K + k0 + colv]
                                   : make_float4(0.f, 0.f, 0.f, 0.f);
            }
            #pragma unroll
            for (int j = 0; j < 2; j++) {
                int idx = t + j * 256;
                int r = idx >> 2, colv = (idx & 3) << 3;
                uint32_t off = (uint32_t)((r * LDP + colv) * 2);
                cp_async16(smem_u32(nxt + 20480 + off), BThi + (size_t)r * K + k0 + colv);
                cp_async16(smem_u32(nxt + 30720 + off), BTlo + (size_t)r * K + k0 + colv);
            }
        }
        CP_COMMIT();

        // ---- compute on current stage ----
        const uint32_t uAh = smem_u32(cur);
        const uint32_t uAl = uAh + 10240;
        const uint32_t uBh = uAh + 20480;
        const uint32_t uBl = uAh + 30720;
        #pragma unroll
        for (int ks = 0; ks < 2; ks++) {
            const int kc = ks * 16;
            uint32_t ah[2][4], al[2][4];
            #pragma unroll
            for (int mf = 0; mf < 2; mf++) {
                uint32_t off = (uint32_t)((wm * 32 + mf * 16 + a_lrow) * 80 + (kc + a_c8) * 2);
                ldmatrix_x4(ah[mf][0], ah[mf][1], ah[mf][2], ah[mf][3], uAh + off);
                ldmatrix_x4(al[mf][0], al[mf][1], al[mf][2], al[mf][3], uAl + off);
            }
            uint32_t bh[8][2], bl[8][2];
            #pragma unroll
            for (int p = 0; p < 4; p++) {
                uint32_t off = (uint32_t)((wn * 64 + p * 16 + b_lrow) * 80 + (kc + b_c8) * 2);
                uint32_t r0, r1, r2, r3;
                ldmatrix_x4(r0, r1, r2, r3, uBh + off);
                bh[2*p][0] = r0; bh[2*p][1] = r1; bh[2*p+1][0] = r2; bh[2*p+1][1] = r3;
                ldmatrix_x4(r0, r1, r2, r3, uBl + off);
                bl[2*p][0] = r0; bl[2*p][1] = r1; bl[2*p+1][0] = r2; bl[2*p+1][1] = r3;
            }
            #pragma unroll
            for (int mf = 0; mf < 2; mf++)
                #pragma unroll
                for (int nf = 0; nf < 8; nf++) {
                    mma_bf16(acc[mf][nf], ah[mf], bh[nf]);
                    mma_bf16(acc[mf][nf], ah[mf], bl[nf]);
                    mma_bf16(acc[mf][nf], al[mf], bh[nf]);
                }
        }

        // convert prefetched A into next stage, then wait B cp.async
        if (more) {
            __nv_bfloat16* sAh = (__nv_bfloat16*)(nxt);
            __nv_bfloat16* sAl = (__nv_bfloat16*)(nxt + 10240);
            #pragma unroll
            for (int j = 0; j < 4; j++) {
                int idx = t + j * 256;
                int r = idx >> 3, colv = (idx & 7) << 2;
                float4 v = areg[j];
                __nv_bfloat16 h0 = __float2bfloat16(v.x), h1 = __float2bfloat16(v.y);
                __nv_bfloat16 h2 = __float2bfloat16(v.z), h3 = __float2bfloat16(v.w);
                uint2 hv, lv;
                hv.x = pack2(h0, h1); hv.y = pack2(h2, h3);
                lv.x = pack2(__float2bfloat16(v.x - __bfloat162float(h0)),
                             __float2bfloat16(v.y - __bfloat162float(h1)));
                lv.y = pack2(__float2bfloat16(v.z - __bfloat162float(h2)),
                             __float2bfloat16(v.w - __bfloat162float(h3)));
                *(uint2*)&sAh[r * LDP + colv] = hv;
                *(uint2*)&sAl[r * LDP + colv] = lv;
            }
        }
        CP_WAIT0();
        __syncthreads();
    }

    // ---- epilogue ----
    const int crow = lane >> 2;
    const int ccol = (lane & 3) << 1;
    #pragma unroll
    for (int mf = 0; mf < 2; mf++) {
        int rbase = row0 + wm * 32 + mf * 16 + crow;
        #pragma unroll
        for (int nf = 0; nf < 8; nf++) {
            int col = wn * 64 + nf * 8 + ccol;
            #pragma unroll
            for (int half = 0; half < 2; half++) {
                int r = rbase + half * 8;
                if (r >= M) continue;
                float v0 = acc[mf][nf][half * 2 + 0];
                float v1 = acc[mf][nf][half * 2 + 1];
                if (bias) { v0 += bias[col]; v1 += bias[col + 1]; }
                if (apply_gelu) {
                    v0 = 0.5f * v0 * (1.0f + erff(v0 * 0.70710678118654752f));
                    v1 = 0.5f * v1 * (1.0f + erff(v1 * 0.70710678118654752f));
                }
                float2 o; o.x = v0; o.y = v1;
                *(float2*)&C[(size_t)r * HID + col] = o;
            }
        }
    }
}

// ================= attention coefficients =================
__global__ __launch_bounds__(256)
void alpha_kernel(const float* __restrict__ asrc, const float* __restrict__ adst) {
    int gtid = blockIdx.x * blockDim.x + threadIdx.x;
    int node = gtid >> 5;
    if (node >= NN) return;
    int lane = threadIdx.x & 31;
    float4 hv = ((const float4*)g_H)[node * 32 + lane];
    float4 av = ((const float4*)asrc)[lane];
    float4 dv = ((const float4*)adst)[lane];
    float s = hv.x * av.x + hv.y * av.y + hv.z * av.z + hv.w * av.w;
    float d = hv.x * dv.x + hv.y * dv.y + hv.z * dv.z + hv.w * dv.w;
    #pragma unroll
    for (int off = 4; off >= 1; off >>= 1) {
        s += __shfl_xor_sync(0xffffffffu, s, off);
        d += __shfl_xor_sync(0xffffffffu, d, off);
    }
    if ((lane & 7) == 0) {
        int head = lane >> 3;
        g_as[node * HEADS + head] = s;
        g_ad[node * HEADS + head] = d;
    }
}

// ================= warp-per-node GAT aggregation (online softmax) =================
__global__ __launch_bounds__(256)
void gat_agg_kernel(const float* __restrict__ bias, float* __restrict__ Xout) {
    int gtid = blockIdx.x * blockDim.x + threadIdx.x;
    int node = gtid >> 5;
    if (node >= NN) return;
    int lane = threadIdx.x & 31;
    int head = lane >> 3;

    const float4* H4 = (const float4*)g_H;
    float ad = g_ad[node * HEADS + head];

    float e0 = g_as[node * HEADS + head] + ad;     // self loop
    e0 = e0 > 0.f ? e0 : 0.2f * e0;
    float m = e0;
    float dsum = 1.0f;
    float4 acc = H4[node * 32 + lane];

    int beg = g_rowptr[node];
    int end = g_rowptr[node + 1];
    for (int i = beg; i < end; i++) {
        int src = g_colsrc[i];
        float e = g_as[src * HEADS + head] + ad;
        e = e > 0.f ? e : 0.2f * e;
        float4 hv = H4[src * 32 + lane];
        float mn = fmaxf(m, e);
        float sc = __expf(m - mn);
        float w  = __expf(e - mn);
        dsum = fmaf(dsum, sc, w);
        acc.x = fmaf(acc.x, sc, w * hv.x);
        acc.y = fmaf(acc.y, sc, w * hv.y);
        acc.z = fmaf(acc.z, sc, w * hv.z);
        acc.w = fmaf(acc.w, sc, w * hv.w);
        m = mn;
    }
    float inv = 1.0f / dsum;
    float4 bv = ((const float4*)bias)[lane];
    float4 o;
    o.x = fmaxf(fmaf(acc.x, inv, bv.x), 0.0f);
    o.y = fmaxf(fmaf(acc.y, inv, bv.y), 0.0f);
    o.z = fmaxf(fmaf(acc.z, inv, bv.z), 0.0f);
    o.w = fmaxf(fmaf(acc.w, inv, bv.w), 0.0f);
    ((float4*)Xout)[node * 32 + lane] = o;
}

// ================= block-per-graph segmented pool =================
__global__ __launch_bounds__(128)
void pool2_kernel(float* __restrict__ out) {
    int g = blockIdx.x, t = threadIdx.x;
    int beg = g_gstart[g], end = g_gstart[g + 1];
    float s = 0.0f;
    for (int r = beg; r < end; r++) s += g_X[(size_t)r * HID + t];
    out[g * HID + t] = s;
}

// ================= launch =================
extern "C" void kernel_launch(void* const* d_in, const int* in_sizes, int n_in,
                              void* d_out, int out_size) {
    const float* nf    = (const float*)d_in[0];
    const int*   ei    = (const int*)d_in[1];
    const int*   batch = (const int*)d_in[2];
    const float* W1    = (const float*)d_in[3];
    const float* b1    = (const float*)d_in[4];
    const float* Wg    = (const float*)d_in[5];
    const float* a_src = (const float*)d_in[6];
    const float* a_dst = (const float*)d_in[7];
    const float* bg    = (const float*)d_in[8];
    float* out = (float*)d_out;

    float *pX, *pH;
    cudaGetSymbolAddress((void**)&pX, g_X);
    cudaGetSymbolAddress((void**)&pH, g_H);
    int* pCursor;
    cudaGetSymbolAddress((void**)&pCursor, g_cursor);
    __nv_bfloat16 *pW1hi, *pW1lo, *pWghi, *pWglo;
    cudaGetSymbolAddress((void**)&pW1hi, g_W1T_hi);
    cudaGetSymbolAddress((void**)&pW1lo, g_W1T_lo);
    cudaGetSymbolAddress((void**)&pWghi, g_WgT_hi);
    cudaGetSymbolAddress((void**)&pWglo, g_WgT_lo);

    cudaFuncSetAttribute(mma_gemm_kernel,
                         cudaFuncAttributeMaxDynamicSharedMemorySize, TCG_SMEM);

    // ---- weight prep ----
    prep_w1_kernel<<<(HID * INDIM + 255) / 256, 256>>>(W1);
    prep_wg_kernel<<<(2 * HID * HID + 255) / 256, 256>>>(Wg);

    // ---- CSR build ----
    const int nsb = (NN + 1023) / 1024;     // 98
    zero_int_kernel<<<(NN + 255) / 256, 256>>>(pCursor, NN);
    hist_kernel<<<(EE + 255) / 256, 256>>>(ei);
    scan_block_kernel<<<nsb, 1024>>>();
    scan_sums_kernel<<<1, 128>>>(nsb);
    scan_add_kernel<<<nsb, 1024>>>();
    copy_cursor_kernel<<<(NN + 255) / 256, 256>>>();
    scatter_kernel<<<(EE + 255) / 256, 256>>>(ei);

    // ---- graph boundaries for pooling ----
    gstart_kernel<<<(NN + 255) / 256, 256>>>(batch);

    const int gemm_grid = (NN + 127) / 128;

    // ---- X = gelu(nf @ W1 + b1) ----
    mma_gemm_kernel<<<gemm_grid, 256, TCG_SMEM>>>(nf, pW1hi, pW1lo, b1, pX, NN, INDIM, 1);

    // ---- GAT layers ----
    for (int l = 0; l < 2; l++) {
        mma_gemm_kernel<<<gemm_grid, 256, TCG_SMEM>>>(
            pX, pWghi + (size_t)l * HID * HID, pWglo + (size_t)l * HID * HID,
            nullptr, pH, NN, HID, 0);
        alpha_kernel<<<(NN * 32 + 255) / 256, 256>>>(a_src + l * HEADS * 32, a_dst + l * HEADS * 32);
        gat_agg_kernel<<<(NN * 32 + 255) / 256, 256>>>(bg + l * HID, pX);
    }

    // ---- pool ----
    pool2_kernel<<<GG, 128>>>(out);
}

// round 6
// speedup vs baseline: 1.9465x; 1.0326x over previous
#include <cuda_runtime.h>
#include <cuda_bf16.h>
#include <math.h>
#include <stdint.h>

#define NN      100000
#define EE      1600000
#define GG      512
#define INDIM   1024
#define HID     128
#define HEADS   4
#define LDP     40          // smem row pitch in bf16 elems (80 B)

// ================= static device scratch =================
__device__ float g_X[NN * HID];
__device__ float g_H[NN * HID];
__device__ float g_as[NN * HEADS];
__device__ float g_ad[NN * HEADS];
__device__ int   g_rowptr[NN + 1];
__device__ int   g_cursor[NN];
__device__ int   g_colsrc[EE];
__device__ int   g_blocksum[128];
__device__ int   g_blockoff[128];
__device__ int   g_gstart[GG + 1];
__device__ __nv_bfloat16 g_W1T_hi[HID * INDIM];   // [n][k]
__device__ __nv_bfloat16 g_W1T_lo[HID * INDIM];
__device__ __nv_bfloat16 g_WgT_hi[2 * HID * HID];
__device__ __nv_bfloat16 g_WgT_lo[2 * HID * HID];

// ================= utility kernels =================
__global__ void zero_int_kernel(int* p, int n) {
    int i = blockIdx.x * blockDim.x + threadIdx.x;
    if (i < n) p[i] = 0;
}
__global__ void hist_kernel(const int* __restrict__ ei) {
    int e = blockIdx.x * blockDim.x + threadIdx.x;
    if (e < EE) atomicAdd(&g_cursor[ei[EE + e]], 1);
}

// ---- 3-phase scan ----
__global__ void scan_block_kernel() {        // grid 98, block 1024
    __shared__ int sm[1024];
    int b = blockIdx.x, t = threadIdx.x;
    int i = b * 1024 + t;
    int v = (i < NN) ? g_cursor[i] : 0;
    sm[t] = v;
    __syncthreads();
    #pragma unroll
    for (int off = 1; off < 1024; off <<= 1) {
        int add = (t >= off) ? sm[t - off] : 0;
        __syncthreads();
        sm[t] += add;
        __syncthreads();
    }
    if (i < NN) g_rowptr[i + 1] = sm[t];
    if (t == 1023) g_blocksum[b] = sm[1023];
}
__global__ void scan_sums_kernel(int nblocks) {  // 1 block, 128 threads
    __shared__ int sm[128];
    int t = threadIdx.x;
    sm[t] = (t < nblocks) ? g_blocksum[t] : 0;
    __syncthreads();
    #pragma unroll
    for (int off = 1; off < 128; off <<= 1) {
        int add = (t >= off) ? sm[t - off] : 0;
        __syncthreads();
        sm[t] += add;
        __syncthreads();
    }
    g_blockoff[t] = (t == 0) ? 0 : sm[t - 1];
}
// adds block offsets AND initializes cursor = exclusive prefix (rowptr[i])
__global__ void scan_add_kernel() {           // grid 98, block 1024
    int b = blockIdx.x, t = threadIdx.x;
    int i = b * 1024 + t;
    if (i < NN) {
        int incl = g_rowptr[i + 1] + g_blockoff[b];
        g_rowptr[i + 1] = incl;
        g_cursor[i] = incl - g_cursor[i];     // exclusive start for scatter
    }
    if (i == 0) g_rowptr[0] = 0;
}
__global__ void scatter_kernel(const int* __restrict__ ei) {
    int e = blockIdx.x * blockDim.x + threadIdx.x;
    if (e < EE) {
        int src = ei[e];
        int dst = ei[EE + e];
        g_colsrc[atomicAdd(&g_cursor[dst], 1)] = src;
    }
}

// ---- graph boundaries from sorted batch ----
__global__ void gstart_kernel(const int* __restrict__ batch) {
    int i = blockIdx.x * blockDim.x + threadIdx.x;
    if (i >= NN) return;
    int b = batch[i];
    int prev = (i == 0) ? -1 : batch[i - 1];
    for (int g = prev + 1; g <= b; g++) g_gstart[g] = i;
    if (i == NN - 1)
        for (int g = b + 1; g <= GG; g++) g_gstart[g] = NN;
}

// ================= weight prep =================
__global__ void prep_w1_kernel(const float* __restrict__ W) {
    int idx = blockIdx.x * blockDim.x + threadIdx.x;
    if (idx >= HID * INDIM) return;
    int n = idx >> 10, k = idx & 1023;
    float w = W[k * HID + n];
    __nv_bfloat16 h = __float2bfloat16(w);
    g_W1T_hi[idx] = h;
    g_W1T_lo[idx] = __float2bfloat16(w - __bfloat162float(h));
}
__global__ void prep_wg_kernel(const float* __restrict__ W) {
    int idx = blockIdx.x * blockDim.x + threadIdx.x;
    if (idx >= 2 * HID * HID) return;
    int l = idx >> 14, n = (idx >> 7) & 127, k = idx & 127;
    float w = W[l * HID * HID + k * HID + n];
    __nv_bfloat16 h = __float2bfloat16(w);
    g_WgT_hi[idx] = h;
    g_WgT_lo[idx] = __float2bfloat16(w - __bfloat162float(h));
}

// ================= mma helpers =================
__device__ __forceinline__ uint32_t smem_u32(const void* p) {
    uint32_t a;
    asm("{ .reg .u64 t; cvta.to.shared.u64 t, %1; cvt.u32.u64 %0, t; }" : "=r"(a) : "l"(p));
    return a;
}
__device__ __forceinline__ void ldmatrix_x4(uint32_t& r0, uint32_t& r1, uint32_t& r2, uint32_t& r3,
                                            uint32_t addr) {
    asm volatile("ldmatrix.sync.aligned.m8n8.x4.shared.b16 {%0,%1,%2,%3}, [%4];"
                 : "=r"(r0), "=r"(r1), "=r"(r2), "=r"(r3) : "r"(addr));
}
__device__ __forceinline__ void mma_bf16(float* c, const uint32_t* a, const uint32_t* b) {
    asm volatile(
        "mma.sync.aligned.m16n8k16.row.col.f32.bf16.bf16.f32 "
        "{%0,%1,%2,%3}, {%4,%5,%6,%7}, {%8,%9}, {%0,%1,%2,%3};"
        : "+f"(c[0]), "+f"(c[1]), "+f"(c[2]), "+f"(c[3])
        : "r"(a[0]), "r"(a[1]), "r"(a[2]), "r"(a[3]), "r"(b[0]), "r"(b[1]));
}
__device__ __forceinline__ uint32_t pack2(__nv_bfloat16 a, __nv_bfloat16 b) {
    __nv_bfloat162 p; p.x = a; p.y = b;
    return *(uint32_t*)&p;
}
__device__ __forceinline__ void cp_async16(uint32_t dst, const void* src) {
    asm volatile("cp.async.cg.shared.global [%0], [%1], 16;" :: "r"(dst), "l"(src));
}
#define CP_COMMIT() asm volatile("cp.async.commit_group;" ::: "memory")
#define CP_WAIT0()  asm volatile("cp.async.wait_group 0;" ::: "memory")

// ================= pipelined HMMA split-bf16 GEMM (+ fused alpha) =================
#define STAGE_BYTES 40960
#define TCG_SMEM    (2 * STAGE_BYTES)

__global__ __launch_bounds__(256)
void mma_gemm_kernel(const float* __restrict__ A,
                     const __nv_bfloat16* __restrict__ BThi,
                     const __nv_bfloat16* __restrict__ BTlo,
                     const float* __restrict__ bias,
                     float* __restrict__ C,
                     int M, int K, int apply_gelu,
                     const float* __restrict__ asrc,   // [128] flat (head-major) or null
                     const float* __restrict__ adst) {
    extern __shared__ char dsm[];

    const int t = threadIdx.x;
    const int lane = t & 31, wid = t >> 5;
    const int wm = wid & 3;
    const int wn = wid >> 2;
    const int row0 = blockIdx.x * 128;

    float acc[2][8][4];
    #pragma unroll
    for (int i = 0; i < 2; i++)
        #pragma unroll
        for (int j = 0; j < 8; j++)
            #pragma unroll
            for (int q = 0; q < 4; q++) acc[i][j][q] = 0.0f;

    const int a_lrow = lane & 15;
    const int a_c8   = (lane >> 4) << 3;
    const int b_lrow = (lane & 7) + ((lane >> 4) << 3);
    const int b_c8   = ((lane >> 3) & 1) << 3;

    const int nchunks = K >> 5;
    float4 areg[4];

    // ---- prologue: chunk 0 ----
    {
        const int k0 = 0;
        #pragma unroll
        for (int j = 0; j < 4; j++) {
            int idx = t + j * 256;
            int r = idx >> 3, colv = (idx & 7) << 2;
            int gr = row0 + r;
            areg[j] = (gr < M) ? *(const float4*)&A[(size_t)gr * K + k0 + colv]
                               : make_float4(0.f, 0.f, 0.f, 0.f);
        }
        char* st = dsm;
        #pragma unroll
        for (int j = 0; j < 2; j++) {
            int idx = t + j * 256;
            int r = idx >> 2, colv = (idx & 3) << 3;
            uint32_t off = (uint32_t)((r * LDP + colv) * 2);
            cp_async16(smem_u32(st + 20480 + off), BThi + (size_t)r * K + k0 + colv);
            cp_async16(smem_u32(st + 30720 + off), BTlo + (size_t)r * K + k0 + colv);
        }
        CP_COMMIT();
        __nv_bfloat16* sAh = (__nv_bfloat16*)(st);
        __nv_bfloat16* sAl = (__nv_bfloat16*)(st + 10240);
        #pragma unroll
        for (int j = 0; j < 4; j++) {
            int idx = t + j * 256;
            int r = idx >> 3, colv = (idx & 7) << 2;
            float4 v = areg[j];
            __nv_bfloat16 h0 = __float2bfloat16(v.x), h1 = __float2bfloat16(v.y);
            __nv_bfloat16 h2 = __float2bfloat16(v.z), h3 = __float2bfloat16(v.w);
            uint2 hv, lv;
            hv.x = pack2(h0, h1); hv.y = pack2(h2, h3);
            lv.x = pack2(__float2bfloat16(v.x - __bfloat162float(h0)),
                         __float2bfloat16(v.y - __bfloat162float(h1)));
            lv.y = pack2(__float2bfloat16(v.z - __bfloat162float(h2)),
                         __float2bfloat16(v.w - __bfloat162float(h3)));
            *(uint2*)&sAh[r * LDP + colv] = hv;
            *(uint2*)&sAl[r * LDP + colv] = lv;
        }
        CP_WAIT0();
        __syncthreads();
    }

    for (int c = 0; c < nchunks; c++) {
        char* cur = dsm + (c & 1) * STAGE_BYTES;
        char* nxt = dsm + ((c + 1) & 1) * STAGE_BYTES;
        const bool more = (c + 1) < nchunks;

        if (more) {
            const int k0 = (c + 1) << 5;
            #pragma unroll
            for (int j = 0; j < 4; j++) {
                int idx = t + j * 256;
                int r = idx >> 3, colv = (idx & 7) << 2;
                int gr = row0 + r;
                areg[j] = (gr < M) ? *(const float4*)&A[(size_t)gr * K + k0 + colv]
                                   : make_float4(0.f, 0.f, 0.f, 0.f);
            }
            #pragma unroll
            for (int j = 0; j < 2; j++) {
                int idx = t + j * 256;
                int r = idx >> 2, colv = (idx & 3) << 3;
                uint32_t off = (uint32_t)((r * LDP + colv) * 2);
                cp_async16(smem_u32(nxt + 20480 + off), BThi + (size_t)r * K + k0 + colv);
                cp_async16(smem_u32(nxt + 30720 + off), BTlo + (size_t)r * K + k0 + colv);
            }
        }
        CP_COMMIT();

        const uint32_t uAh = smem_u32(cur);
        const uint32_t uAl = uAh + 10240;
        const uint32_t uBh = uAh + 20480;
        const uint32_t uBl = uAh + 30720;
        #pragma unroll
        for (int ks = 0; ks < 2; ks++) {
            const int kc = ks * 16;
            uint32_t ah[2][4], al[2][4];
            #pragma unroll
            for (int mf = 0; mf < 2; mf++) {
                uint32_t off = (uint32_t)((wm * 32 + mf * 16 + a_lrow) * 80 + (kc + a_c8) * 2);
                ldmatrix_x4(ah[mf][0], ah[mf][1], ah[mf][2], ah[mf][3], uAh + off);
                ldmatrix_x4(al[mf][0], al[mf][1], al[mf][2], al[mf][3], uAl + off);
            }
            uint32_t bh[8][2], bl[8][2];
            #pragma unroll
            for (int p = 0; p < 4; p++) {
                uint32_t off = (uint32_t)((wn * 64 + p * 16 + b_lrow) * 80 + (kc + b_c8) * 2);
                uint32_t r0, r1, r2, r3;
                ldmatrix_x4(r0, r1, r2, r3, uBh + off);
                bh[2*p][0] = r0; bh[2*p][1] = r1; bh[2*p+1][0] = r2; bh[2*p+1][1] = r3;
                ldmatrix_x4(r0, r1, r2, r3, uBl + off);
                bl[2*p][0] = r0; bl[2*p][1] = r1; bl[2*p+1][0] = r2; bl[2*p+1][1] = r3;
            }
            #pragma unroll
            for (int mf = 0; mf < 2; mf++)
                #pragma unroll
                for (int nf = 0; nf < 8; nf++) {
                    mma_bf16(acc[mf][nf], ah[mf], bh[nf]);
                    mma_bf16(acc[mf][nf], ah[mf], bl[nf]);
                    mma_bf16(acc[mf][nf], al[mf], bh[nf]);
                }
        }

        if (more) {
            __nv_bfloat16* sAh = (__nv_bfloat16*)(nxt);
            __nv_bfloat16* sAl = (__nv_bfloat16*)(nxt + 10240);
            #pragma unroll
            for (int j = 0; j < 4; j++) {
                int idx = t + j * 256;
                int r = idx >> 3, colv = (idx & 7) << 2;
                float4 v = areg[j];
                __nv_bfloat16 h0 = __float2bfloat16(v.x), h1 = __float2bfloat16(v.y);
                __nv_bfloat16 h2 = __float2bfloat16(v.z), h3 = __float2bfloat16(v.w);
                uint2 hv, lv;
                hv.x = pack2(h0, h1); hv.y = pack2(h2, h3);
                lv.x = pack2(__float2bfloat16(v.x - __bfloat162float(h0)),
                             __float2bfloat16(v.y - __bfloat162float(h1)));
                lv.y = pack2(__float2bfloat16(v.z - __bfloat162float(h2)),
                             __float2bfloat16(v.w - __bfloat162float(h3)));
                *(uint2*)&sAh[r * LDP + colv] = hv;
                *(uint2*)&sAl[r * LDP + colv] = lv;
            }
        }
        CP_WAIT0();
        __syncthreads();
    }

    // ---- epilogue: store C, optionally fused alpha dot-products ----
    const int crow = lane >> 2;
    const int ccol = (lane & 3) << 1;
    // alpha partials: [mf][half][head_local(2)]
    float aS[2][2][2], aD[2][2][2];
    #pragma unroll
    for (int i = 0; i < 2; i++)
        #pragma unroll
        for (int j = 0; j < 2; j++)
            { aS[i][j][0]=aS[i][j][1]=aD[i][j][0]=aD[i][j][1]=0.f; }

    #pragma unroll
    for (int mf = 0; mf < 2; mf++) {
        int rbase = row0 + wm * 32 + mf * 16 + crow;
        #pragma unroll
        for (int nf = 0; nf < 8; nf++) {
            int col = wn * 64 + nf * 8 + ccol;
            int hl = nf >> 2;   // head within this wn half
            #pragma unroll
            for (int half = 0; half < 2; half++) {
                int r = rbase + half * 8;
                float v0 = acc[mf][nf][half * 2 + 0];
                float v1 = acc[mf][nf][half * 2 + 1];
                if (asrc) {
                    aS[mf][half][hl] += v0 * asrc[col] + v1 * asrc[col + 1];
                    aD[mf][half][hl] += v0 * adst[col] + v1 * adst[col + 1];
                }
                if (r >= M) continue;
                if (bias) { v0 += bias[col]; v1 += bias[col + 1]; }
                if (apply_gelu) {
                    v0 = 0.5f * v0 * (1.0f + erff(v0 * 0.70710678118654752f));
                    v1 = 0.5f * v1 * (1.0f + erff(v1 * 0.70710678118654752f));
                }
                float2 o; o.x = v0; o.y = v1;
                *(float2*)&C[(size_t)r * HID + col] = o;
            }
        }
    }

    if (asrc) {
        // reduce across the 4 lanes sharing a row (lane & 3)
        #pragma unroll
        for (int mf = 0; mf < 2; mf++)
            #pragma unroll
            for (int half = 0; half < 2; half++)
                #pragma unroll
                for (int hl = 0; hl < 2; hl++) {
                    float s = aS[mf][half][hl], d = aD[mf][half][hl];
                    s += __shfl_xor_sync(0xffffffffu, s, 1);
                    s += __shfl_xor_sync(0xffffffffu, s, 2);
                    d += __shfl_xor_sync(0xffffffffu, d, 1);
                    d += __shfl_xor_sync(0xffffffffu, d, 2);
                    aS[mf][half][hl] = s; aD[mf][half][hl] = d;
                }
        if ((lane & 3) == 0) {
            #pragma unroll
            for (int mf = 0; mf < 2; mf++)
                #pragma unroll
                for (int half = 0; half < 2; half++) {
                    int r = row0 + wm * 32 + mf * 16 + crow + half * 8;
                    if (r < M) {
                        int hbase = r * HEADS + wn * 2;
                        g_as[hbase + 0] = aS[mf][half][0];
                        g_as[hbase + 1] = aS[mf][half][1];
                        g_ad[hbase + 0] = aD[mf][half][0];
                        g_ad[hbase + 1] = aD[mf][half][1];
                    }
                }
        }
    }
}

// ================= warp-per-node GAT aggregation (online softmax) =================
__global__ __launch_bounds__(256)
void gat_agg_kernel(const float* __restrict__ bias, float* __restrict__ Xout) {
    int gtid = blockIdx.x * blockDim.x + threadIdx.x;
    int node = gtid >> 5;
    if (node >= NN) return;
    int lane = threadIdx.x & 31;
    int head = lane >> 3;

    const float4* H4 = (const float4*)g_H;
    float ad = g_ad[node * HEADS + head];

    float e0 = g_as[node * HEADS + head] + ad;     // self loop
    e0 = e0 > 0.f ? e0 : 0.2f * e0;
    float m = e0;
    float dsum = 1.0f;
    float4 acc = H4[node * 32 + lane];

    int beg = g_rowptr[node];
    int end = g_rowptr[node + 1];
    for (int i = beg; i < end; i++) {
        int src = g_colsrc[i];
        float e = g_as[src * HEADS + head] + ad;
        e = e > 0.f ? e : 0.2f * e;
        float4 hv = H4[src * 32 + lane];
        float mn = fmaxf(m, e);
        float sc = __expf(m - mn);
        float w  = __expf(e - mn);
        dsum = fmaf(dsum, sc, w);
        acc.x = fmaf(acc.x, sc, w * hv.x);
        acc.y = fmaf(acc.y, sc, w * hv.y);
        acc.z = fmaf(acc.z, sc, w * hv.z);
        acc.w = fmaf(acc.w, sc, w * hv.w);
        m = mn;
    }
    float inv = 1.0f / dsum;
    float4 bv = ((const float4*)bias)[lane];
    float4 o;
    o.x = fmaxf(fmaf(acc.x, inv, bv.x), 0.0f);
    o.y = fmaxf(fmaf(acc.y, inv, bv.y), 0.0f);
    o.z = fmaxf(fmaf(acc.z, inv, bv.z), 0.0f);
    o.w = fmaxf(fmaf(acc.w, inv, bv.w), 0.0f);
    ((float4*)Xout)[node * 32 + lane] = o;
}

// ================= block-per-graph segmented pool =================
__global__ __launch_bounds__(128)
void pool2_kernel(float* __restrict__ out) {
    int g = blockIdx.x, t = threadIdx.x;
    int beg = g_gstart[g], end = g_gstart[g + 1];
    float s = 0.0f;
    for (int r = beg; r < end; r++) s += g_X[(size_t)r * HID + t];
    out[g * HID + t] = s;
}

// ================= launch =================
extern "C" void kernel_launch(void* const* d_in, const int* in_sizes, int n_in,
                              void* d_out, int out_size) {
    const float* nf    = (const float*)d_in[0];
    const int*   ei    = (const int*)d_in[1];
    const int*   batch = (const int*)d_in[2];
    const float* W1    = (const float*)d_in[3];
    const float* b1    = (const float*)d_in[4];
    const float* Wg    = (const float*)d_in[5];
    const float* a_src = (const float*)d_in[6];
    const float* a_dst = (const float*)d_in[7];
    const float* bg    = (const float*)d_in[8];
    float* out = (float*)d_out;

    float *pX, *pH;
    cudaGetSymbolAddress((void**)&pX, g_X);
    cudaGetSymbolAddress((void**)&pH, g_H);
    int* pCursor;
    cudaGetSymbolAddress((void**)&pCursor, g_cursor);
    __nv_bfloat16 *pW1hi, *pW1lo, *pWghi, *pWglo;
    cudaGetSymbolAddress((void**)&pW1hi, g_W1T_hi);
    cudaGetSymbolAddress((void**)&pW1lo, g_W1T_lo);
    cudaGetSymbolAddress((void**)&pWghi, g_WgT_hi);
    cudaGetSymbolAddress((void**)&pWglo, g_WgT_lo);

    cudaFuncSetAttribute(mma_gemm_kernel,
                         cudaFuncAttributeMaxDynamicSharedMemorySize, TCG_SMEM);

    // ---- weight prep ----
    prep_w1_kernel<<<(HID * INDIM + 255) / 256, 256>>>(W1);
    prep_wg_kernel<<<(2 * HID * HID + 255) / 256, 256>>>(Wg);

    // ---- CSR build ----
    const int nsb = (NN + 1023) / 1024;     // 98
    zero_int_kernel<<<(NN + 255) / 256, 256>>>(pCursor, NN);
    hist_kernel<<<(EE + 255) / 256, 256>>>(ei);
    scan_block_kernel<<<nsb, 1024>>>();
    scan_sums_kernel<<<1, 128>>>(nsb);
    scan_add_kernel<<<nsb, 1024>>>();        // also initializes cursor
    scatter_kernel<<<(EE + 255) / 256, 256>>>(ei);

    // ---- graph boundaries for pooling ----
    gstart_kernel<<<(NN + 255) / 256, 256>>>(batch);

    const int gemm_grid = (NN + 127) / 128;

    // ---- X = gelu(nf @ W1 + b1) ----
    mma_gemm_kernel<<<gemm_grid, 256, TCG_SMEM>>>(nf, pW1hi, pW1lo, b1, pX, NN, INDIM, 1,
                                                  nullptr, nullptr);

    // ---- GAT layers (alpha fused into GEMM epilogue) ----
    for (int l = 0; l < 2; l++) {
        mma_gemm_kernel<<<gemm_grid, 256, TCG_SMEM>>>(
            pX, pWghi + (size_t)l * HID * HID, pWglo + (size_t)l * HID * HID,
            nullptr, pH, NN, HID, 0,
            a_src + l * HEADS * 32, a_dst + l * HEADS * 32);
        gat_agg_kernel<<<(NN * 32 + 255) / 256, 256>>>(bg + l * HID, pX);
    }

    // ---- pool ----
    pool2_kernel<<<GG, 128>>>(out);
}